// round 6
// baseline (speedup 1.0000x reference)
#include <cuda_runtime.h>
#include <stdint.h>

// out[b,d] = x[b,d] * |W[d,d]|, fused single kernel.
// Each thread owns 8 fixed element columns (two adjacent float4s), so each
// warp moves 1024B contiguous per iteration (read and write), improving DRAM
// page locality vs 512B. blockDim=128 => float4-pair index mod 128 == tid,
// so the two diag float4s are loop-invariant per thread.
__global__ void __launch_bounds__(128) diag_mul_kernel(
    const float4* __restrict__ x4,
    const float* __restrict__ W,
    float4* __restrict__ out4,
    long n8, int D) {
    // This thread's 8 diagonal elements: columns 8*tid .. 8*tid+7.
    int c = threadIdx.x * 8;
    float4 d0, d1;
    d0.x = fabsf(__ldg(&W[(size_t)(c + 0) * (D + 1)]));
    d0.y = fabsf(__ldg(&W[(size_t)(c + 1) * (D + 1)]));
    d0.z = fabsf(__ldg(&W[(size_t)(c + 2) * (D + 1)]));
    d0.w = fabsf(__ldg(&W[(size_t)(c + 3) * (D + 1)]));
    d1.x = fabsf(__ldg(&W[(size_t)(c + 4) * (D + 1)]));
    d1.y = fabsf(__ldg(&W[(size_t)(c + 5) * (D + 1)]));
    d1.z = fabsf(__ldg(&W[(size_t)(c + 6) * (D + 1)]));
    d1.w = fabsf(__ldg(&W[(size_t)(c + 7) * (D + 1)]));

    const long stride = (long)gridDim.x * blockDim.x;  // multiple of 128
    for (long i = (long)blockIdx.x * blockDim.x + threadIdx.x; i < n8; i += stride) {
        long j = 2 * i;
        float4 a = __ldcs(&x4[j]);
        float4 b = __ldcs(&x4[j + 1]);
        a.x *= d0.x; a.y *= d0.y; a.z *= d0.z; a.w *= d0.w;
        b.x *= d1.x; b.y *= d1.y; b.z *= d1.z; b.w *= d1.w;
        __stcs(&out4[j], a);
        __stcs(&out4[j + 1], b);
    }
}

extern "C" void kernel_launch(void* const* d_in, const int* in_sizes, int n_in,
                              void* d_out, int out_size) {
    const float* x = (const float*)d_in[0];
    const float* W = (const float*)d_in[1];
    float* out = (float*)d_out;

    const int D = 1024;
    const long n8 = (long)out_size / 8;  // 2^23 float4-pairs for 65536x1024

    // 2368 blocks x 128 threads; grid-stride covers n8.
    int blocks = 148 * 16;
    diag_mul_kernel<<<blocks, 128>>>(
        reinterpret_cast<const float4*>(x), W,
        reinterpret_cast<float4*>(out), n8, D);
}

// round 7
// speedup vs baseline: 1.0801x; 1.0801x over previous
#include <cuda_runtime.h>
#include <stdint.h>

// out[b,d] = x[b,d] * |W[d,d]|, fused single kernel.
// Grid-stride, blockDim=256, D/4=256 float4 column groups:
// (i mod 256) == threadIdx.x for every iteration, so each thread's diag
// float4 is loop-invariant -> loaded once in the prologue.
// Streaming hints on the zero-reuse x/out streams.
// Grid = 148 SMs x 8 blocks = one fully-resident persistent wave.
__global__ void __launch_bounds__(256) diag_mul_kernel(
    const float4* __restrict__ x4,
    const float* __restrict__ W,
    float4* __restrict__ out4,
    long n4, int D) {
    // This thread's 4 diagonal elements: columns 4*tid .. 4*tid+3.
    int c = threadIdx.x * 4;
    float4 d;
    d.x = fabsf(__ldg(&W[(size_t)(c + 0) * (D + 1)]));
    d.y = fabsf(__ldg(&W[(size_t)(c + 1) * (D + 1)]));
    d.z = fabsf(__ldg(&W[(size_t)(c + 2) * (D + 1)]));
    d.w = fabsf(__ldg(&W[(size_t)(c + 3) * (D + 1)]));

    const long stride = (long)gridDim.x * blockDim.x;  // multiple of 256
    for (long i = (long)blockIdx.x * blockDim.x + threadIdx.x; i < n4; i += stride) {
        float4 v = __ldcs(&x4[i]);
        v.x *= d.x;
        v.y *= d.y;
        v.z *= d.z;
        v.w *= d.w;
        __stcs(&out4[i], v);
    }
}

extern "C" void kernel_launch(void* const* d_in, const int* in_sizes, int n_in,
                              void* d_out, int out_size) {
    const float* x = (const float*)d_in[0];
    const float* W = (const float*)d_in[1];
    float* out = (float*)d_out;

    const int D = 1024;
    const long n4 = (long)out_size / 4;  // 2^24 for 65536x1024

    // One persistent wave: 8 blocks/SM (32 regs, 8 warps/block -> 64 warps/SM).
    int blocks = 148 * 8;  // 1184
    diag_mul_kernel<<<blocks, 256>>>(
        reinterpret_cast<const float4*>(x), W,
        reinterpret_cast<float4*>(out), n4, D);
}

// round 8
// speedup vs baseline: 1.1548x; 1.0691x over previous
#include <cuda_runtime.h>
#include <stdint.h>

// out[b,d] = x[b,d] * |W[d,d]|, fused single kernel. CONVERGED SHAPE (R4):
// - blockDim=256, D/4=256 float4 column groups => (i mod 256)==threadIdx.x
//   for every grid-stride iteration, so each thread's diag float4 is
//   loop-invariant and loaded once in the prologue (W diag is L2-resident).
// - __ldcs/__stcs: x/out have zero reuse, evict-first keeps L2 clean.
// - 32 regs, ~90% occupancy, 2368 blocks (2 waves).
// Measured at the HBM roofline for 1:1 R/W streams: ~6.08 TB/s (76% of spec).
__global__ void __launch_bounds__(256) diag_mul_kernel(
    const float4* __restrict__ x4,
    const float* __restrict__ W,
    float4* __restrict__ out4,
    long n4, int D) {
    // This thread's 4 diagonal elements: columns 4*tid .. 4*tid+3.
    int c = threadIdx.x * 4;
    float4 d;
    d.x = fabsf(__ldg(&W[(size_t)(c + 0) * (D + 1)]));
    d.y = fabsf(__ldg(&W[(size_t)(c + 1) * (D + 1)]));
    d.z = fabsf(__ldg(&W[(size_t)(c + 2) * (D + 1)]));
    d.w = fabsf(__ldg(&W[(size_t)(c + 3) * (D + 1)]));

    const long stride = (long)gridDim.x * blockDim.x;  // multiple of 256
    for (long i = (long)blockIdx.x * blockDim.x + threadIdx.x; i < n4; i += stride) {
        float4 v = __ldcs(&x4[i]);
        v.x *= d.x;
        v.y *= d.y;
        v.z *= d.z;
        v.w *= d.w;
        __stcs(&out4[i], v);
    }
}

extern "C" void kernel_launch(void* const* d_in, const int* in_sizes, int n_in,
                              void* d_out, int out_size) {
    const float* x = (const float*)d_in[0];
    const float* W = (const float*)d_in[1];
    float* out = (float*)d_out;

    const int D = 1024;
    const long n4 = (long)out_size / 4;  // 2^24 for 65536x1024

    int blocks = 148 * 16;  // 2368; 8 resident blocks/SM at 32 regs
    diag_mul_kernel<<<blocks, 256>>>(
        reinterpret_cast<const float4*>(x), W,
        reinterpret_cast<float4*>(out), n4, D);
}